// round 9
// baseline (speedup 1.0000x reference)
#include <cuda_runtime.h>
#include <cuda_bf16.h>
#include <math.h>
#include <stdint.h>

// Problem constants
#define BB   16
#define TT   256
#define VV   25
#define DM   128
#define HH   8
#define HD   16
#define MAXT 300
#define SEQS (BB*VV)          // 400
#define NTOK (SEQS*TT)        // 102400
#define NBIAS (2*MAXT-1)      // 599
#define PART (HH*NTOK*HD)     // per q/k/v head-major part size (elements)
#define LOG2E 1.4426950408889634f

// GEMM tiling (bf16): BK=64, 3-stage pipeline
#define BM 128
#define BN 128
#define BK 64
#define NSTG 3
#define ASTR 72               // streaming A row stride (144B, phase-16 conflict-free)
#define AFSTR 136             // fused-LN fixed A row stride (272B)
#define BSTR 136              // B row stride
#define SA (BM*ASTR)          // 9216 halves
#define SB (BK*BSTR)          // 8704 halves
#define STG (SA + SB)         // 17920 halves per stage
#define AFSZ (BM*AFSTR)       // 17408 halves (fixed A buffer)
#define GEMM_SMEM (NSTG*STG*2)          // 107520 bytes (streaming variant)
#define QKV_SMEM ((AFSZ + NSTG*SB)*2)   // 87040 bytes (fused-LN variant)

// weight-prep segment offsets (bf16 copies)
#define WOFF_QKV  0
#define WOFF_PROJ 49152
#define WOFF_W1   65536
#define WOFF_W2   131072
#define WTOTAL    196608

typedef __nv_bfloat16 bf16;

// ---------------- scratch (device globals; no runtime allocation) -------------
__device__ bf16  g_qkv [NTOK*3*DM];   // q/k/v, head-major [3][H][NTOK][16]
__device__ bf16  g_attn[NTOK*DM];     // attention output, head-major
__device__ float g_xf  [NTOK*DM];     // after proj + residual (fp32)
__device__ bf16  g_z   [NTOK*DM];     // LN2 output
__device__ bf16  g_h   [NTOK*4*DM];   // FFN hidden
__device__ bf16  g_w   [WTOTAL];      // bf16 weights

// ---------------- helpers ------------------------------------------------------
__device__ __forceinline__ uint32_t packbf(float lo, float hi) {
    uint32_t r;
    asm("cvt.rn.bf16x2.f32 %0, %1, %2;" : "=r"(r) : "f"(hi), "f"(lo));
    return r;
}
__device__ __forceinline__ float2 unpk(uint32_t u) {
    __nv_bfloat162 h = *reinterpret_cast<__nv_bfloat162*>(&u);
    return make_float2(__bfloat162float(h.x), __bfloat162float(h.y));
}
__device__ __forceinline__ float ex2(float x) {
    float r;
    asm("ex2.approx.ftz.f32 %0, %1;" : "=f"(r) : "f"(x));
    return r;
}
__device__ __forceinline__ void mma16(float* c, const uint32_t* a, const uint32_t* b) {
    asm volatile(
        "mma.sync.aligned.m16n8k16.row.col.f32.bf16.bf16.f32 "
        "{%0,%1,%2,%3}, {%4,%5,%6,%7}, {%8,%9}, {%0,%1,%2,%3};"
        : "+f"(c[0]), "+f"(c[1]), "+f"(c[2]), "+f"(c[3])
        : "r"(a[0]), "r"(a[1]), "r"(a[2]), "r"(a[3]), "r"(b[0]), "r"(b[1]));
}
__device__ __forceinline__ void ldm_x4(uint32_t* r, uint32_t addr) {
    asm volatile("ldmatrix.sync.aligned.m8n8.x4.shared.b16 {%0,%1,%2,%3}, [%4];"
        : "=r"(r[0]), "=r"(r[1]), "=r"(r[2]), "=r"(r[3]) : "r"(addr));
}
__device__ __forceinline__ void ldm_x2(uint32_t* r, uint32_t addr) {
    asm volatile("ldmatrix.sync.aligned.m8n8.x2.shared.b16 {%0,%1}, [%2];"
        : "=r"(r[0]), "=r"(r[1]) : "r"(addr));
}
__device__ __forceinline__ void ldm_x2_t(uint32_t* r, uint32_t addr) {
    asm volatile("ldmatrix.sync.aligned.m8n8.x2.trans.shared.b16 {%0,%1}, [%2];"
        : "=r"(r[0]), "=r"(r[1]) : "r"(addr));
}
__device__ __forceinline__ void cp16(uint32_t dst, const void* src) {
    asm volatile("cp.async.cg.shared.global [%0], [%1], 16;" :: "r"(dst), "l"(src));
}
__device__ __forceinline__ void cp_commit() {
    asm volatile("cp.async.commit_group;" ::: "memory");
}
template<int N>
__device__ __forceinline__ void cp_wait() {
    asm volatile("cp.async.wait_group %0;" :: "n"(N) : "memory");
}
__device__ __forceinline__ int gather_off(int row) {
    int seq = row / TT, t = row % TT;
    int b = seq / VV, v = seq % VV;
    return ((b*TT + t)*VV + v) * DM;
}

// ---------------- weight prep: fp32 -> bf16 -------------------------------------
__global__ void wprep_kernel(const float* __restrict__ qkvw,
                             const float* __restrict__ projw,
                             const float* __restrict__ w1,
                             const float* __restrict__ w2,
                             bf16* __restrict__ dst)
{
    int i = blockIdx.x * blockDim.x + threadIdx.x;
    if (i >= WTOTAL) return;
    float v;
    if      (i < WOFF_PROJ) v = qkvw[i];
    else if (i < WOFF_W1)   v = projw[i - WOFF_PROJ];
    else if (i < WOFF_W2)   v = w1[i - WOFF_W1];
    else                    v = w2[i - WOFF_W2];
    dst[i] = __float2bfloat16(v);
}

// ---------------- bf16 tensor-core GEMM (BK=64, 3-stage) ------------------------
// EPI 1: + bias + gather(x via extra) -> Cf fp32; fused LayerNorm -> Cb bf16
// EPI 2: gelu_exact(+ bias) -> Cb bf16              (FFN1)
// EPI 3: + bias + extra[row] -> scatter fp32 Cf     (FFN2)
// EPI 4: + bias -> scatter head-major q/k/v (Cb)    (QKV)
// AG 1:     A is head-major [H][NTOK][16] bf16
// FUSELN 1: A = LayerNorm(gather(extra)) computed in-kernel into fixed smem
//           (lng/lnb are LN1 params; `extra` is x fp32)
template<int KDIM, int NDIM, int EPI, int AG, int FUSELN>
__global__ void __launch_bounds__(256, 2)
mma_gemm(const bf16* __restrict__ A,
         const bf16* __restrict__ B,
         const float* __restrict__ bias,
         const float* __restrict__ extra,
         float* __restrict__ Cf,
         bf16* __restrict__ Cb,
         const float* __restrict__ lng,
         const float* __restrict__ lnb)
{
    extern __shared__ bf16 smem[];
    uint32_t sbase = (uint32_t)__cvta_generic_to_shared(smem);

    const int tid  = threadIdx.x;
    const int bx   = blockIdx.x, by = blockIdx.y;
    const int lane = tid & 31, warp = tid >> 5;
    const int wm   = (warp & 1) * 64;
    const int wn   = (warp >> 1) * 32;
    const int g    = lane >> 2, tig = lane & 3;

    const int NK = KDIM / BK;
    const int ASTRX = FUSELN ? AFSTR : ASTR;
    float acc[4][4][4] = {};

    auto load_tile = [&](int kt, int slot) {
        if (!FUSELN) {
            uint32_t sa = sbase + 2*(slot*STG);
            #pragma unroll
            for (int i = 0; i < 4; i++) {
                int id = tid + i*256;
                int r = id >> 3, c8 = (id & 7) * 8;
                int row = by*BM + r;
                if (AG) {
                    int k = kt*BK + c8;
                    cp16(sa + 2*(r*ASTR + c8),
                         A + ((long)((k >> 4)*NTOK + row))*HD + (k & 15));
                } else {
                    cp16(sa + 2*(r*ASTR + c8), A + (long)row*KDIM + kt*BK + c8);
                }
            }
        }
        uint32_t sbB = sbase + 2*(FUSELN ? (AFSZ + slot*SB) : (slot*STG + SA));
        #pragma unroll
        for (int j = 0; j < 4; j++) {
            int id = tid + j*256;
            int r = id >> 4, c8 = (id & 15) * 8;
            cp16(sbB + 2*(r*BSTR + c8), B + (long)(kt*BK + r)*NDIM + bx*BN + c8);
        }
    };

    // prologue: stages 0,1
    load_tile(0, 0); cp_commit();
    load_tile(1, 1); cp_commit();

    // fused LN1 into fixed A buffer (each warp: 16 rows)
    if (FUSELN) {
        #pragma unroll 1
        for (int i = 0; i < 16; i++) {
            int rl = warp*16 + i;
            int m  = by*BM + rl;
            int seq = m / TT, t = m % TT;
            int b = seq / VV, v = seq % VV;
            const float* src = extra + ((b*TT + t)*VV + v) * DM;

            float4 xv = *(const float4*)(src + lane*4);
            float s = xv.x + xv.y + xv.z + xv.w;
            #pragma unroll
            for (int o = 16; o > 0; o >>= 1) s += __shfl_xor_sync(0xffffffffu, s, o);
            float mean = s * (1.0f / DM);
            float d0 = xv.x - mean, d1 = xv.y - mean;
            float d2 = xv.z - mean, d3 = xv.w - mean;
            float q = d0*d0 + d1*d1 + d2*d2 + d3*d3;
            #pragma unroll
            for (int o = 16; o > 0; o >>= 1) q += __shfl_xor_sync(0xffffffffu, q, o);
            float inv = rsqrtf(q * (1.0f / DM) + 1e-5f);

            float4 gv = *(const float4*)(lng + lane*4);
            float4 bv = *(const float4*)(lnb + lane*4);
            uint2 r;
            r.x = packbf(d0*inv*gv.x + bv.x, d1*inv*gv.y + bv.y);
            r.y = packbf(d2*inv*gv.z + bv.z, d3*inv*gv.w + bv.w);
            *(uint2*)(smem + rl*AFSTR + lane*4) = r;
        }
    }

    const int a_roff = (lane & 7) + ((lane >> 3) & 1) * 8;
    const int a_coff = (lane >> 4) * 8;
    const int b_roff = lane & 15;

    #pragma unroll 1
    for (int kt = 0; kt < NK; kt++) {
        if (kt + 1 < NK) cp_wait<1>(); else cp_wait<0>();
        __syncthreads();
        if (kt + 2 < NK) { load_tile(kt + 2, (kt + 2) % 3); cp_commit(); }

        uint32_t abase = FUSELN ? (sbase + 2*(kt*BK))
                                : (sbase + 2*((kt % 3)*STG));
        uint32_t bbase = sbase + 2*(FUSELN ? (AFSZ + (kt % 3)*SB)
                                           : ((kt % 3)*STG + SA));
        #pragma unroll
        for (int ks = 0; ks < 4; ks++) {
            uint32_t af[4][4], bf[4][2];
            #pragma unroll
            for (int mi = 0; mi < 4; mi++)
                ldm_x4(af[mi], abase + 2*((wm + mi*16 + a_roff)*ASTRX + ks*16 + a_coff));
            #pragma unroll
            for (int ni = 0; ni < 4; ni++)
                ldm_x2_t(bf[ni], bbase + 2*((ks*16 + b_roff)*BSTR + wn + ni*8));
            #pragma unroll
            for (int mi = 0; mi < 4; mi++)
                #pragma unroll
                for (int ni = 0; ni < 4; ni++)
                    mma16(acc[mi][ni], af[mi], bf[ni]);
        }
    }

    // ---------------- epilogue ----------------
    if (EPI == 1) {
        __syncthreads();
        float* red = (float*)smem;
        const int wngrp = warp >> 1;

        float rsum[4][2], rsq[4][2];
        #pragma unroll
        for (int mi = 0; mi < 4; mi++) {
            #pragma unroll
            for (int rr = 0; rr < 2; rr++) {
                int rloc = wm + mi*16 + rr*8 + g;
                int row  = by*BM + rloc;
                int go   = gather_off(row);
                float ls = 0.f, lq = 0.f;
                #pragma unroll
                for (int ni = 0; ni < 4; ni++) {
                    int col = wn + ni*8 + 2*tig;
                    float vx = acc[mi][ni][rr*2+0] + bias[col]   + extra[go + col];
                    float vy = acc[mi][ni][rr*2+1] + bias[col+1] + extra[go + col + 1];
                    acc[mi][ni][rr*2+0] = vx;
                    acc[mi][ni][rr*2+1] = vy;
                    float2 r = {vx, vy};
                    *(float2*)&Cf[(long)row*DM + col] = r;
                    ls += vx + vy;
                    lq += vx*vx + vy*vy;
                }
                rsum[mi][rr] = ls; rsq[mi][rr] = lq;
            }
        }
        #pragma unroll
        for (int mi = 0; mi < 4; mi++)
            #pragma unroll
            for (int rr = 0; rr < 2; rr++) {
                #pragma unroll
                for (int o = 1; o <= 2; o <<= 1) {
                    rsum[mi][rr] += __shfl_xor_sync(0xffffffffu, rsum[mi][rr], o);
                    rsq[mi][rr]  += __shfl_xor_sync(0xffffffffu, rsq[mi][rr],  o);
                }
            }
        if (tig == 0) {
            #pragma unroll
            for (int mi = 0; mi < 4; mi++)
                #pragma unroll
                for (int rr = 0; rr < 2; rr++) {
                    int rloc = wm + mi*16 + rr*8 + g;
                    red[(rloc*4 + wngrp)*2 + 0] = rsum[mi][rr];
                    red[(rloc*4 + wngrp)*2 + 1] = rsq[mi][rr];
                }
        }
        __syncthreads();
        #pragma unroll
        for (int mi = 0; mi < 4; mi++) {
            #pragma unroll
            for (int rr = 0; rr < 2; rr++) {
                int rloc = wm + mi*16 + rr*8 + g;
                int row  = by*BM + rloc;
                float s = 0.f, q = 0.f;
                #pragma unroll
                for (int w2 = 0; w2 < 4; w2++) {
                    s += red[(rloc*4 + w2)*2 + 0];
                    q += red[(rloc*4 + w2)*2 + 1];
                }
                float mean = s * (1.0f/DM);
                float var  = q * (1.0f/DM) - mean*mean;
                float inv  = rsqrtf(var + 1e-5f);
                #pragma unroll
                for (int ni = 0; ni < 4; ni++) {
                    int col = wn + ni*8 + 2*tig;
                    float zx = (acc[mi][ni][rr*2+0] - mean)*inv*lng[col]   + lnb[col];
                    float zy = (acc[mi][ni][rr*2+1] - mean)*inv*lng[col+1] + lnb[col+1];
                    *(uint32_t*)&Cb[(long)row*DM + col] = packbf(zx, zy);
                }
            }
        }
        return;
    }

    #pragma unroll
    for (int mi = 0; mi < 4; mi++) {
        #pragma unroll
        for (int rr = 0; rr < 2; rr++) {
            int row = by*BM + wm + mi*16 + rr*8 + g;
            int go = 0;
            if (EPI == 3) go = gather_off(row);
            #pragma unroll
            for (int ni = 0; ni < 4; ni++) {
                int col = bx*BN + wn + ni*8 + 2*tig;
                float vx = acc[mi][ni][rr*2 + 0] + bias[col];
                float vy = acc[mi][ni][rr*2 + 1] + bias[col + 1];
                if (EPI == 2) {
                    vx = 0.5f * vx * (1.0f + erff(vx * 0.70710678118654752f));
                    vy = 0.5f * vy * (1.0f + erff(vy * 0.70710678118654752f));
                    *(uint32_t*)&Cb[(long)row*NDIM + col] = packbf(vx, vy);
                } else if (EPI == 3) {
                    vx += extra[(long)row*DM + col];
                    vy += extra[(long)row*DM + col + 1];
                    float2 r = {vx, vy};
                    *(float2*)&Cf[go + col] = r;
                } else {  // EPI 4: head-major q/k/v
                    int part = col >> 7, rem = col & 127;
                    int hh = rem >> 4, d = rem & 15;
                    *(uint32_t*)&Cb[(long)part*PART + ((long)hh*NTOK + row)*HD + d] =
                        packbf(vx, vy);
                }
            }
        }
    }
}

// ---------------- bf16 tensor-core attention (unchanged from round 8) -----------
__global__ void __launch_bounds__(256, 4)
attn_bf16_kernel(const bf16* __restrict__ qkv,
                 const float* __restrict__ logit_scale,
                 const float* __restrict__ rpb,
                 bf16* __restrict__ out)
{
    __shared__ __align__(16) bf16 Qs[TT*24];
    __shared__ __align__(16) bf16 Ks[TT*24];
    __shared__ __align__(16) bf16 Vs[TT*24];
    __shared__ float bs[NBIAS + 1];

    const int seq = blockIdx.x, h = blockIdx.y;
    const int t    = threadIdx.x;
    const int lane = t & 31, w = t >> 5;
    const int g    = lane >> 2, tig = lane & 3;

    for (int i = t; i < NBIAS; i += 256) bs[i] = rpb[h*NBIAS + i] * LOG2E;

    const long idx = ((long)h*NTOK + seq*TT + t) * HD;
    const float scale = __expf(fminf(logit_scale[h], 4.6051701859880914f));

    {
        uint4 qu0 = *(const uint4*)(qkv + idx);
        uint4 qu1 = *(const uint4*)(qkv + idx + 8);
        uint4 ku0 = *(const uint4*)(qkv + PART + idx);
        uint4 ku1 = *(const uint4*)(qkv + PART + idx + 8);
        uint4 vu0 = *(const uint4*)(qkv + 2L*PART + idx);
        uint4 vu1 = *(const uint4*)(qkv + 2L*PART + idx + 8);

        uint32_t uq[8] = {qu0.x,qu0.y,qu0.z,qu0.w, qu1.x,qu1.y,qu1.z,qu1.w};
        uint32_t uk[8] = {ku0.x,ku0.y,ku0.z,ku0.w, ku1.x,ku1.y,ku1.z,ku1.w};
        float q[16], k[16];
        float qs = 0.f, ks = 0.f;
        #pragma unroll
        for (int j = 0; j < 8; j++) {
            float2 fq = unpk(uq[j]), fk = unpk(uk[j]);
            q[2*j] = fq.x; q[2*j+1] = fq.y;
            k[2*j] = fk.x; k[2*j+1] = fk.y;
            qs += fq.x*fq.x + fq.y*fq.y;
            ks += fk.x*fk.x + fk.y*fk.y;
        }
        float qf = scale * 0.25f * LOG2E / fmaxf(sqrtf(qs), 1e-12f);
        float kf = 1.0f / fmaxf(sqrtf(ks), 1e-12f);
        uint32_t wq[8], wk[8];
        #pragma unroll
        for (int j = 0; j < 8; j++) {
            wq[j] = packbf(q[2*j]*qf, q[2*j+1]*qf);
            wk[j] = packbf(k[2*j]*kf, k[2*j+1]*kf);
        }
        *(uint4*)&Qs[t*24]     = make_uint4(wq[0],wq[1],wq[2],wq[3]);
        *(uint4*)&Qs[t*24 + 8] = make_uint4(wq[4],wq[5],wq[6],wq[7]);
        *(uint4*)&Ks[t*24]     = make_uint4(wk[0],wk[1],wk[2],wk[3]);
        *(uint4*)&Ks[t*24 + 8] = make_uint4(wk[4],wk[5],wk[6],wk[7]);
        *(uint4*)&Vs[t*24]      = vu0;
        *(uint4*)&Vs[t*24 + 8]  = vu1;
        *(uint4*)&Vs[t*24 + 16] = make_uint4(0x00003F80u, 0u, 0u, 0u);  // ones col
    }
    __syncthreads();

    uint32_t sQ = (uint32_t)__cvta_generic_to_shared(Qs);
    uint32_t sK = (uint32_t)__cvta_generic_to_shared(Ks);
    uint32_t sV = (uint32_t)__cvta_generic_to_shared(Vs);

    const int m0 = w * 32;
    const int fr = (lane & 7) + ((lane >> 3) & 1) * 8;
    const int fc = (lane >> 4) * 8;

    uint32_t qa[2][4];
    #pragma unroll
    for (int mi = 0; mi < 2; mi++)
        ldm_x4(qa[mi], sQ + 2*((m0 + mi*16 + fr)*24 + fc));

    float oacc[2][3][4] = {};

    #pragma unroll 1
    for (int cc = 0; cc < 8; cc++) {
        const int s0 = cc * 32;
        float sacc[2][4][4];

        #pragma unroll
        for (int mi = 0; mi < 2; mi++)
            #pragma unroll
            for (int ni = 0; ni < 4; ni++) {
                int d = m0 + mi*16 + g - (s0 + ni*8 + 2*tig) + (MAXT-1);
                sacc[mi][ni][0] = bs[d];
                sacc[mi][ni][1] = bs[d-1];
                sacc[mi][ni][2] = bs[d+8];
                sacc[mi][ni][3] = bs[d+7];
            }

        #pragma unroll
        for (int ni = 0; ni < 4; ni++) {
            uint32_t kb[2];
            ldm_x2(kb, sK + 2*((s0 + ni*8 + (lane & 7))*24 + ((lane >> 3) & 1)*8));
            #pragma unroll
            for (int mi = 0; mi < 2; mi++)
                mma16(sacc[mi][ni], qa[mi], kb);
        }

        #pragma unroll
        for (int mi = 0; mi < 2; mi++)
            #pragma unroll
            for (int ni = 0; ni < 4; ni++) {
                sacc[mi][ni][0] = ex2(sacc[mi][ni][0]);
                sacc[mi][ni][1] = ex2(sacc[mi][ni][1]);
                sacc[mi][ni][2] = ex2(sacc[mi][ni][2]);
                sacc[mi][ni][3] = ex2(sacc[mi][ni][3]);
            }

        #pragma unroll
        for (int kk = 0; kk < 2; kk++) {
            uint32_t pa[2][4];
            #pragma unroll
            for (int mi = 0; mi < 2; mi++) {
                pa[mi][0] = packbf(sacc[mi][2*kk  ][0], sacc[mi][2*kk  ][1]);
                pa[mi][1] = packbf(sacc[mi][2*kk  ][2], sacc[mi][2*kk  ][3]);
                pa[mi][2] = packbf(sacc[mi][2*kk+1][0], sacc[mi][2*kk+1][1]);
                pa[mi][3] = packbf(sacc[mi][2*kk+1][2], sacc[mi][2*kk+1][3]);
            }
            #pragma unroll
            for (int nd = 0; nd < 3; nd++) {
                uint32_t vb[2];
                ldm_x2_t(vb, sV + 2*((s0 + kk*16 + (lane & 15))*24 + nd*8));
                #pragma unroll
                for (int mi = 0; mi < 2; mi++)
                    mma16(oacc[mi][nd], pa[mi], vb);
            }
        }
    }

    #pragma unroll
    for (int mi = 0; mi < 2; mi++) {
        #pragma unroll
        for (int rr = 0; rr < 2; rr++) {
            float l = __shfl_sync(0xffffffffu, oacc[mi][2][rr*2], lane & ~3);
            float il = 1.0f / l;
            int row = m0 + mi*16 + rr*8 + g;
            long oidx = ((long)h*NTOK + seq*TT + row) * HD;
            #pragma unroll
            for (int nd = 0; nd < 2; nd++) {
                *(uint32_t*)&out[oidx + nd*8 + 2*tig] =
                    packbf(oacc[mi][nd][rr*2+0]*il, oacc[mi][nd][rr*2+1]*il);
            }
        }
    }
}

// -------------------------------- launch ----------------------------------------
extern "C" void kernel_launch(void* const* d_in, const int* in_sizes, int n_in,
                              void* d_out, int out_size)
{
    const float* x     = (const float*)d_in[0];
    const float* ln1g  = (const float*)d_in[1];
    const float* ln1b  = (const float*)d_in[2];
    const float* qkvw  = (const float*)d_in[3];
    const float* qkvb  = (const float*)d_in[4];
    const float* projw = (const float*)d_in[5];
    const float* projb = (const float*)d_in[6];
    const float* ls    = (const float*)d_in[7];
    const float* rpb   = (const float*)d_in[8];
    const float* ln2g  = (const float*)d_in[9];
    const float* ln2b  = (const float*)d_in[10];
    const float* w1    = (const float*)d_in[11];
    const float* b1    = (const float*)d_in[12];
    const float* w2    = (const float*)d_in[13];
    const float* b2    = (const float*)d_in[14];
    float* out = (float*)d_out;

    bf16 *qkv, *attn, *z, *hb, *wbuf;
    float *xf;
    cudaGetSymbolAddress((void**)&qkv,  g_qkv);
    cudaGetSymbolAddress((void**)&attn, g_attn);
    cudaGetSymbolAddress((void**)&xf,   g_xf);
    cudaGetSymbolAddress((void**)&z,    g_z);
    cudaGetSymbolAddress((void**)&hb,   g_h);
    cudaGetSymbolAddress((void**)&wbuf, g_w);

    cudaFuncSetAttribute(mma_gemm<128, 384, 4, 0, 1>, cudaFuncAttributeMaxDynamicSharedMemorySize, GEMM_SMEM);
    cudaFuncSetAttribute(mma_gemm<128, 128, 1, 1, 0>, cudaFuncAttributeMaxDynamicSharedMemorySize, GEMM_SMEM);
    cudaFuncSetAttribute(mma_gemm<128, 512, 2, 0, 0>, cudaFuncAttributeMaxDynamicSharedMemorySize, GEMM_SMEM);
    cudaFuncSetAttribute(mma_gemm<512, 128, 3, 0, 0>, cudaFuncAttributeMaxDynamicSharedMemorySize, GEMM_SMEM);

    // 0) weights -> bf16
    wprep_kernel<<<(WTOTAL + 255)/256, 256>>>(qkvw, projw, w1, w2, wbuf);
    // 1) fused gather+LN1+QKV -> head-major bf16 q/k/v
    mma_gemm<128, 384, 4, 0, 1><<<dim3(3, NTOK/BM), 256, QKV_SMEM>>>(
        nullptr, wbuf + WOFF_QKV, qkvb, x, nullptr, qkv, ln1g, ln1b);
    // 2) bf16 tensor-core attention
    attn_bf16_kernel<<<dim3(SEQS, HH), 256>>>(qkv, ls, rpb, attn);
    // 3) proj + residual -> xf (fp32), fused LN2 -> z (bf16)
    mma_gemm<128, 128, 1, 1, 0><<<dim3(1, NTOK/BM), 256, GEMM_SMEM>>>(
        attn, wbuf + WOFF_PROJ, projb, x, xf, z, ln2g, ln2b);
    // 4) FFN1 + exact GELU -> h (bf16)
    mma_gemm<128, 512, 2, 0, 0><<<dim3(4, NTOK/BM), 256, GEMM_SMEM>>>(
        z, wbuf + WOFF_W1, b1, nullptr, nullptr, hb, nullptr, nullptr);
    // 5) FFN2 + residual -> scatter fp32 (B,T,V,D) output
    mma_gemm<512, 128, 3, 0, 0><<<dim3(1, NTOK/BM), 256, GEMM_SMEM>>>(
        hb, wbuf + WOFF_W2, b2, xf, out, nullptr, nullptr, nullptr);
}

// round 10
// speedup vs baseline: 1.1366x; 1.1366x over previous
#include <cuda_runtime.h>
#include <cuda_bf16.h>
#include <math.h>
#include <stdint.h>

// Problem constants
#define BB   16
#define TT   256
#define VV   25
#define DM   128
#define HH   8
#define HD   16
#define MAXT 300
#define SEQS (BB*VV)          // 400
#define NTOK (SEQS*TT)        // 102400
#define NBIAS (2*MAXT-1)      // 599
#define PART (HH*NTOK*HD)     // per q/k/v head-major part size (elements)
#define LOG2E 1.4426950408889634f

// GEMM tiling (bf16) — round-8 proven configuration
#define BM 128
#define BN 128
#define BK 32
#define NSTG 4
#define ASTR 40               // A row stride in halves
#define BSTR (BN + 8)         // 136 halves
#define SA (BM*ASTR)
#define SB (BK*BSTR)
#define STG (SA + SB)
#define GEMM_SMEM (NSTG*STG*2)  // 75776 bytes

// fused LN1+QKV kernel layout (halves)
#define QNN 384
#define QAF 136                  // fixed A row stride
#define QAFSZ (BM*QAF)           // 17408 halves
#define QSB (BK*136)             // 4352 halves per B stage
#define QKV_SMEM ((QAFSZ + 4*QSB)*2)   // 69632 bytes

// weight-prep segment offsets (bf16 copies)
#define WOFF_QKV  0
#define WOFF_PROJ 49152
#define WOFF_W1   65536
#define WOFF_W2   131072
#define WTOTAL    196608

typedef __nv_bfloat16 bf16;

// ---------------- scratch (device globals; no runtime allocation) -------------
__device__ bf16  g_qkv [NTOK*3*DM];   // q/k/v, head-major [3][H][NTOK][16]
__device__ bf16  g_attn[NTOK*DM];     // attention output, head-major
__device__ float g_xf  [NTOK*DM];     // after proj + residual (fp32)
__device__ bf16  g_z   [NTOK*DM];     // LN2 output
__device__ bf16  g_h   [NTOK*4*DM];   // FFN hidden
__device__ bf16  g_w   [WTOTAL];      // bf16 weights

// ---------------- helpers ------------------------------------------------------
__device__ __forceinline__ uint32_t packbf(float lo, float hi) {
    uint32_t r;
    asm("cvt.rn.bf16x2.f32 %0, %1, %2;" : "=r"(r) : "f"(hi), "f"(lo));
    return r;
}
__device__ __forceinline__ float2 unpk(uint32_t u) {
    __nv_bfloat162 h = *reinterpret_cast<__nv_bfloat162*>(&u);
    return make_float2(__bfloat162float(h.x), __bfloat162float(h.y));
}
__device__ __forceinline__ float ex2(float x) {
    float r;
    asm("ex2.approx.ftz.f32 %0, %1;" : "=f"(r) : "f"(x));
    return r;
}
__device__ __forceinline__ void mma16(float* c, const uint32_t* a, const uint32_t* b) {
    asm volatile(
        "mma.sync.aligned.m16n8k16.row.col.f32.bf16.bf16.f32 "
        "{%0,%1,%2,%3}, {%4,%5,%6,%7}, {%8,%9}, {%0,%1,%2,%3};"
        : "+f"(c[0]), "+f"(c[1]), "+f"(c[2]), "+f"(c[3])
        : "r"(a[0]), "r"(a[1]), "r"(a[2]), "r"(a[3]), "r"(b[0]), "r"(b[1]));
}
__device__ __forceinline__ void ldm_x4(uint32_t* r, uint32_t addr) {
    asm volatile("ldmatrix.sync.aligned.m8n8.x4.shared.b16 {%0,%1,%2,%3}, [%4];"
        : "=r"(r[0]), "=r"(r[1]), "=r"(r[2]), "=r"(r[3]) : "r"(addr));
}
__device__ __forceinline__ void ldm_x2(uint32_t* r, uint32_t addr) {
    asm volatile("ldmatrix.sync.aligned.m8n8.x2.shared.b16 {%0,%1}, [%2];"
        : "=r"(r[0]), "=r"(r[1]) : "r"(addr));
}
__device__ __forceinline__ void ldm_x2_t(uint32_t* r, uint32_t addr) {
    asm volatile("ldmatrix.sync.aligned.m8n8.x2.trans.shared.b16 {%0,%1}, [%2];"
        : "=r"(r[0]), "=r"(r[1]) : "r"(addr));
}
__device__ __forceinline__ void cp16(uint32_t dst, const void* src) {
    asm volatile("cp.async.cg.shared.global [%0], [%1], 16;" :: "r"(dst), "l"(src));
}
__device__ __forceinline__ void cp_commit() {
    asm volatile("cp.async.commit_group;" ::: "memory");
}
template<int N>
__device__ __forceinline__ void cp_wait() {
    asm volatile("cp.async.wait_group %0;" :: "n"(N) : "memory");
}
__device__ __forceinline__ int gather_off(int row) {
    int seq = row / TT, t = row % TT;
    int b = seq / VV, v = seq % VV;
    return ((b*TT + t)*VV + v) * DM;
}

// ---------------- weight prep: fp32 -> bf16 -------------------------------------
__global__ void wprep_kernel(const float* __restrict__ qkvw,
                             const float* __restrict__ projw,
                             const float* __restrict__ w1,
                             const float* __restrict__ w2,
                             bf16* __restrict__ dst)
{
    int i = blockIdx.x * blockDim.x + threadIdx.x;
    if (i >= WTOTAL) return;
    float v;
    if      (i < WOFF_PROJ) v = qkvw[i];
    else if (i < WOFF_W1)   v = projw[i - WOFF_PROJ];
    else if (i < WOFF_W2)   v = w1[i - WOFF_W1];
    else                    v = w2[i - WOFF_W2];
    dst[i] = __float2bfloat16(v);
}

// ---------------- fused LN1 + QKV GEMM -------------------------------------------
// Fixed A buffer (LayerNormed rows, K=128 resident), B streamed through a 4-slot
// ring across 12 tiles (3 N-passes x 4 k-tiles). Scatters q/k/v head-major + bias.
__global__ void __launch_bounds__(256, 2)
qkvln_kernel(const float* __restrict__ x,
             const float* __restrict__ lng,
             const float* __restrict__ lnb,
             const bf16* __restrict__ wq,
             const float* __restrict__ qkvb,
             bf16* __restrict__ qkv)
{
    extern __shared__ bf16 sm[];
    uint32_t sb = (uint32_t)__cvta_generic_to_shared(sm);

    const int tid  = threadIdx.x;
    const int by   = blockIdx.x;
    const int lane = tid & 31, warp = tid >> 5;
    const int wm   = (warp & 1) * 64;
    const int wn   = (warp >> 1) * 32;
    const int g    = lane >> 2, tig = lane & 3;

    auto loadB = [&](int tt) {
        int pass = tt >> 2, kt = tt & 3, slot = tt & 3;
        #pragma unroll
        for (int j = 0; j < 2; j++) {
            int id = tid + j*256;
            int r = id >> 4, c8 = (id & 15) * 8;
            cp16(sb + 2*(QAFSZ + slot*QSB + r*136 + c8),
                 wq + (long)(kt*BK + r)*QNN + pass*BN + c8);
        }
    };
    loadB(0); cp_commit();
    loadB(1); cp_commit();
    loadB(2); cp_commit();

    // LN1 into fixed A buffer while B prologue flies (each warp: 16 rows)
    #pragma unroll 1
    for (int i = 0; i < 16; i++) {
        int rl = warp*16 + i;
        int m  = by*BM + rl;
        int seq = m / TT, t = m % TT;
        int b = seq / VV, v = seq % VV;
        const float* src = x + ((b*TT + t)*VV + v) * DM;

        float4 xv = *(const float4*)(src + lane*4);
        float s = xv.x + xv.y + xv.z + xv.w;
        #pragma unroll
        for (int o = 16; o > 0; o >>= 1) s += __shfl_xor_sync(0xffffffffu, s, o);
        float mean = s * (1.0f / DM);
        float d0 = xv.x - mean, d1 = xv.y - mean;
        float d2 = xv.z - mean, d3 = xv.w - mean;
        float q = d0*d0 + d1*d1 + d2*d2 + d3*d3;
        #pragma unroll
        for (int o = 16; o > 0; o >>= 1) q += __shfl_xor_sync(0xffffffffu, q, o);
        float inv = rsqrtf(q * (1.0f / DM) + 1e-5f);

        float4 gv = *(const float4*)(lng + lane*4);
        float4 bv = *(const float4*)(lnb + lane*4);
        uint2 r;
        r.x = packbf(d0*inv*gv.x + bv.x, d1*inv*gv.y + bv.y);
        r.y = packbf(d2*inv*gv.z + bv.z, d3*inv*gv.w + bv.w);
        *(uint2*)(sm + rl*QAF + lane*4) = r;
    }

    const int a_roff = (lane & 7) + ((lane >> 3) & 1) * 8;
    const int a_coff = (lane >> 4) * 8;
    const int b_roff = lane & 15;

    float acc[4][4][4];

    #pragma unroll 1
    for (int tt = 0; tt < 12; tt++) {
        cp_wait<2>();
        __syncthreads();          // covers LN A visibility (tt=0) + slot reuse
        if (tt + 3 < 12) loadB(tt + 3);
        cp_commit();              // unconditional: keeps group counting exact

        const int pass = tt >> 2, kt = tt & 3, slot = tt & 3;
        if (kt == 0) {
            #pragma unroll
            for (int mi = 0; mi < 4; mi++)
                #pragma unroll
                for (int ni = 0; ni < 4; ni++)
                    #pragma unroll
                    for (int e = 0; e < 4; e++) acc[mi][ni][e] = 0.f;
        }

        uint32_t bbase = sb + 2*(QAFSZ + slot*QSB);
        #pragma unroll
        for (int ks = 0; ks < 2; ks++) {
            uint32_t af[4][4], bf[4][2];
            #pragma unroll
            for (int mi = 0; mi < 4; mi++)
                ldm_x4(af[mi], sb + 2*((wm + mi*16 + a_roff)*QAF
                                       + kt*BK + ks*16 + a_coff));
            #pragma unroll
            for (int ni = 0; ni < 4; ni++)
                ldm_x2_t(bf[ni], bbase + 2*((ks*16 + b_roff)*136 + wn + ni*8));
            #pragma unroll
            for (int mi = 0; mi < 4; mi++)
                #pragma unroll
                for (int ni = 0; ni < 4; ni++)
                    mma16(acc[mi][ni], af[mi], bf[ni]);
        }

        if (kt == 3) {
            // per-pass epilogue: + bias, scatter head-major q/k/v
            #pragma unroll
            for (int mi = 0; mi < 4; mi++) {
                #pragma unroll
                for (int rr = 0; rr < 2; rr++) {
                    int row = by*BM + wm + mi*16 + rr*8 + g;
                    #pragma unroll
                    for (int ni = 0; ni < 4; ni++) {
                        int col = pass*BN + wn + ni*8 + 2*tig;
                        float vx = acc[mi][ni][rr*2 + 0] + qkvb[col];
                        float vy = acc[mi][ni][rr*2 + 1] + qkvb[col + 1];
                        int part = col >> 7, rem = col & 127;
                        int hh = rem >> 4, d = rem & 15;
                        *(uint32_t*)&qkv[(long)part*PART
                                         + ((long)hh*NTOK + row)*HD + d] =
                            packbf(vx, vy);
                    }
                }
            }
        }
    }
}

// ---------------- bf16 tensor-core GEMM (round-8 proven) ------------------------
// EPI 1: + bias + gather(x) -> xf (Cf fp32); fused LayerNorm -> z (Cb bf16)
// EPI 2: gelu_exact(+ bias) -> Cb bf16            (FFN1)
// EPI 3: + bias + extra[row] -> scatter fp32 out  (FFN2)
// AG 1: A is head-major [H][NTOK][16] bf16
template<int KDIM, int NDIM, int EPI, int AG>
__global__ void __launch_bounds__(256, 2)
mma_gemm(const bf16* __restrict__ A,
         const bf16* __restrict__ B,
         const float* __restrict__ bias,
         const float* __restrict__ extra,
         float* __restrict__ Cf,
         bf16* __restrict__ Cb,
         const float* __restrict__ lng,
         const float* __restrict__ lnb)
{
    extern __shared__ bf16 smem[];
    uint32_t sbase = (uint32_t)__cvta_generic_to_shared(smem);

    const int tid  = threadIdx.x;
    const int bx   = blockIdx.x, by = blockIdx.y;
    const int lane = tid & 31, warp = tid >> 5;
    const int wm   = (warp & 1) * 64;
    const int wn   = (warp >> 1) * 32;
    const int g    = lane >> 2, tig = lane & 3;

    const int NK = KDIM / BK;
    float acc[4][4][4] = {};

    auto load_tile = [&](int kt, int slot) {
        uint32_t sb = sbase + 2*(slot*STG);
        #pragma unroll
        for (int i = 0; i < 2; i++) {
            int id = tid + i*256;
            int r = id >> 2, c8 = (id & 3) * 8;
            uint32_t dst = sb + 2*(r*ASTR + c8);
            int row = by*BM + r;
            if (AG) {
                int k = kt*BK + c8;
                cp16(dst, A + ((long)((k >> 4)*NTOK + row))*HD + (k & 15));
            } else {
                cp16(dst, A + (long)row*KDIM + kt*BK + c8);
            }
        }
        #pragma unroll
        for (int j = 0; j < 2; j++) {
            int id = tid + j*256;
            int r = id >> 4, c8 = (id & 15) * 8;
            uint32_t dst = sb + 2*(SA + r*BSTR + c8);
            cp16(dst, B + (long)(kt*BK + r)*NDIM + bx*BN + c8);
        }
    };

    #pragma unroll
    for (int s = 0; s < NSTG-1; s++) {
        if (s < NK) load_tile(s, s);
        cp_commit();
    }

    const int a_roff = (lane & 7) + ((lane >> 3) & 1) * 8;
    const int a_coff = (lane >> 4) * 8;
    const int b_roff = lane & 15;

    #pragma unroll 1
    for (int kt = 0; kt < NK; kt++) {
        cp_wait<NSTG-2>();
        __syncthreads();
        int lt = kt + NSTG - 1;
        if (lt < NK) load_tile(lt, lt & (NSTG-1));
        cp_commit();

        uint32_t abase = sbase + 2*((kt & (NSTG-1))*STG);
        uint32_t bbase = abase + 2*SA;

        #pragma unroll
        for (int ks = 0; ks < 2; ks++) {
            uint32_t af[4][4], bf[4][2];
            #pragma unroll
            for (int mi = 0; mi < 4; mi++)
                ldm_x4(af[mi], abase + 2*((wm + mi*16 + a_roff)*ASTR + ks*16 + a_coff));
            #pragma unroll
            for (int ni = 0; ni < 4; ni++)
                ldm_x2_t(bf[ni], bbase + 2*((ks*16 + b_roff)*BSTR + wn + ni*8));
            #pragma unroll
            for (int mi = 0; mi < 4; mi++)
                #pragma unroll
                for (int ni = 0; ni < 4; ni++)
                    mma16(acc[mi][ni], af[mi], bf[ni]);
        }
    }

    // ---------------- epilogue ----------------
    if (EPI == 1) {
        __syncthreads();
        float* red = (float*)smem;
        const int wngrp = warp >> 1;

        float rsum[4][2], rsq[4][2];
        #pragma unroll
        for (int mi = 0; mi < 4; mi++) {
            #pragma unroll
            for (int rr = 0; rr < 2; rr++) {
                int rloc = wm + mi*16 + rr*8 + g;
                int row  = by*BM + rloc;
                int go   = gather_off(row);
                float ls = 0.f, lq = 0.f;
                #pragma unroll
                for (int ni = 0; ni < 4; ni++) {
                    int col = wn + ni*8 + 2*tig;
                    float vx = acc[mi][ni][rr*2+0] + bias[col]   + extra[go + col];
                    float vy = acc[mi][ni][rr*2+1] + bias[col+1] + extra[go + col + 1];
                    acc[mi][ni][rr*2+0] = vx;
                    acc[mi][ni][rr*2+1] = vy;
                    float2 r = {vx, vy};
                    *(float2*)&Cf[(long)row*DM + col] = r;
                    ls += vx + vy;
                    lq += vx*vx + vy*vy;
                }
                rsum[mi][rr] = ls; rsq[mi][rr] = lq;
            }
        }
        #pragma unroll
        for (int mi = 0; mi < 4; mi++)
            #pragma unroll
            for (int rr = 0; rr < 2; rr++) {
                #pragma unroll
                for (int o = 1; o <= 2; o <<= 1) {
                    rsum[mi][rr] += __shfl_xor_sync(0xffffffffu, rsum[mi][rr], o);
                    rsq[mi][rr]  += __shfl_xor_sync(0xffffffffu, rsq[mi][rr],  o);
                }
            }
        if (tig == 0) {
            #pragma unroll
            for (int mi = 0; mi < 4; mi++)
                #pragma unroll
                for (int rr = 0; rr < 2; rr++) {
                    int rloc = wm + mi*16 + rr*8 + g;
                    red[(rloc*4 + wngrp)*2 + 0] = rsum[mi][rr];
                    red[(rloc*4 + wngrp)*2 + 1] = rsq[mi][rr];
                }
        }
        __syncthreads();
        #pragma unroll
        for (int mi = 0; mi < 4; mi++) {
            #pragma unroll
            for (int rr = 0; rr < 2; rr++) {
                int rloc = wm + mi*16 + rr*8 + g;
                int row  = by*BM + rloc;
                float s = 0.f, q = 0.f;
                #pragma unroll
                for (int w2 = 0; w2 < 4; w2++) {
                    s += red[(rloc*4 + w2)*2 + 0];
                    q += red[(rloc*4 + w2)*2 + 1];
                }
                float mean = s * (1.0f/DM);
                float var  = q * (1.0f/DM) - mean*mean;
                float inv  = rsqrtf(var + 1e-5f);
                #pragma unroll
                for (int ni = 0; ni < 4; ni++) {
                    int col = wn + ni*8 + 2*tig;
                    float zx = (acc[mi][ni][rr*2+0] - mean)*inv*lng[col]   + lnb[col];
                    float zy = (acc[mi][ni][rr*2+1] - mean)*inv*lng[col+1] + lnb[col+1];
                    *(uint32_t*)&Cb[(long)row*DM + col] = packbf(zx, zy);
                }
            }
        }
        return;
    }

    #pragma unroll
    for (int mi = 0; mi < 4; mi++) {
        #pragma unroll
        for (int rr = 0; rr < 2; rr++) {
            int row = by*BM + wm + mi*16 + rr*8 + g;
            int go = 0;
            if (EPI == 3) go = gather_off(row);
            #pragma unroll
            for (int ni = 0; ni < 4; ni++) {
                int col = bx*BN + wn + ni*8 + 2*tig;
                float vx = acc[mi][ni][rr*2 + 0] + bias[col];
                float vy = acc[mi][ni][rr*2 + 1] + bias[col + 1];
                if (EPI == 2) {
                    vx = 0.5f * vx * (1.0f + erff(vx * 0.70710678118654752f));
                    vy = 0.5f * vy * (1.0f + erff(vy * 0.70710678118654752f));
                    *(uint32_t*)&Cb[(long)row*NDIM + col] = packbf(vx, vy);
                } else {  // EPI 3
                    vx += extra[(long)row*DM + col];
                    vy += extra[(long)row*DM + col + 1];
                    float2 r = {vx, vy};
                    *(float2*)&Cf[go + col] = r;
                }
            }
        }
    }
}

// ---------------- bf16 tensor-core attention (unchanged round-8) ----------------
__global__ void __launch_bounds__(256, 4)
attn_bf16_kernel(const bf16* __restrict__ qkv,
                 const float* __restrict__ logit_scale,
                 const float* __restrict__ rpb,
                 bf16* __restrict__ out)
{
    __shared__ __align__(16) bf16 Qs[TT*24];
    __shared__ __align__(16) bf16 Ks[TT*24];
    __shared__ __align__(16) bf16 Vs[TT*24];
    __shared__ float bs[NBIAS + 1];

    const int seq = blockIdx.x, h = blockIdx.y;
    const int t    = threadIdx.x;
    const int lane = t & 31, w = t >> 5;
    const int g    = lane >> 2, tig = lane & 3;

    for (int i = t; i < NBIAS; i += 256) bs[i] = rpb[h*NBIAS + i] * LOG2E;

    const long idx = ((long)h*NTOK + seq*TT + t) * HD;
    const float scale = __expf(fminf(logit_scale[h], 4.6051701859880914f));

    {
        uint4 qu0 = *(const uint4*)(qkv + idx);
        uint4 qu1 = *(const uint4*)(qkv + idx + 8);
        uint4 ku0 = *(const uint4*)(qkv + PART + idx);
        uint4 ku1 = *(const uint4*)(qkv + PART + idx + 8);
        uint4 vu0 = *(const uint4*)(qkv + 2L*PART + idx);
        uint4 vu1 = *(const uint4*)(qkv + 2L*PART + idx + 8);

        uint32_t uq[8] = {qu0.x,qu0.y,qu0.z,qu0.w, qu1.x,qu1.y,qu1.z,qu1.w};
        uint32_t uk[8] = {ku0.x,ku0.y,ku0.z,ku0.w, ku1.x,ku1.y,ku1.z,ku1.w};
        float q[16], k[16];
        float qs = 0.f, ks = 0.f;
        #pragma unroll
        for (int j = 0; j < 8; j++) {
            float2 fq = unpk(uq[j]), fk = unpk(uk[j]);
            q[2*j] = fq.x; q[2*j+1] = fq.y;
            k[2*j] = fk.x; k[2*j+1] = fk.y;
            qs += fq.x*fq.x + fq.y*fq.y;
            ks += fk.x*fk.x + fk.y*fk.y;
        }
        float qf = scale * 0.25f * LOG2E / fmaxf(sqrtf(qs), 1e-12f);
        float kf = 1.0f / fmaxf(sqrtf(ks), 1e-12f);
        uint32_t wq[8], wk[8];
        #pragma unroll
        for (int j = 0; j < 8; j++) {
            wq[j] = packbf(q[2*j]*qf, q[2*j+1]*qf);
            wk[j] = packbf(k[2*j]*kf, k[2*j+1]*kf);
        }
        *(uint4*)&Qs[t*24]     = make_uint4(wq[0],wq[1],wq[2],wq[3]);
        *(uint4*)&Qs[t*24 + 8] = make_uint4(wq[4],wq[5],wq[6],wq[7]);
        *(uint4*)&Ks[t*24]     = make_uint4(wk[0],wk[1],wk[2],wk[3]);
        *(uint4*)&Ks[t*24 + 8] = make_uint4(wk[4],wk[5],wk[6],wk[7]);
        *(uint4*)&Vs[t*24]      = vu0;
        *(uint4*)&Vs[t*24 + 8]  = vu1;
        *(uint4*)&Vs[t*24 + 16] = make_uint4(0x00003F80u, 0u, 0u, 0u);  // ones col
    }
    __syncthreads();

    uint32_t sQ = (uint32_t)__cvta_generic_to_shared(Qs);
    uint32_t sK = (uint32_t)__cvta_generic_to_shared(Ks);
    uint32_t sV = (uint32_t)__cvta_generic_to_shared(Vs);

    const int m0 = w * 32;
    const int fr = (lane & 7) + ((lane >> 3) & 1) * 8;
    const int fc = (lane >> 4) * 8;

    uint32_t qa[2][4];
    #pragma unroll
    for (int mi = 0; mi < 2; mi++)
        ldm_x4(qa[mi], sQ + 2*((m0 + mi*16 + fr)*24 + fc));

    float oacc[2][3][4] = {};

    #pragma unroll 1
    for (int cc = 0; cc < 8; cc++) {
        const int s0 = cc * 32;
        float sacc[2][4][4];

        #pragma unroll
        for (int mi = 0; mi < 2; mi++)
            #pragma unroll
            for (int ni = 0; ni < 4; ni++) {
                int d = m0 + mi*16 + g - (s0 + ni*8 + 2*tig) + (MAXT-1);
                sacc[mi][ni][0] = bs[d];
                sacc[mi][ni][1] = bs[d-1];
                sacc[mi][ni][2] = bs[d+8];
                sacc[mi][ni][3] = bs[d+7];
            }

        #pragma unroll
        for (int ni = 0; ni < 4; ni++) {
            uint32_t kb[2];
            ldm_x2(kb, sK + 2*((s0 + ni*8 + (lane & 7))*24 + ((lane >> 3) & 1)*8));
            #pragma unroll
            for (int mi = 0; mi < 2; mi++)
                mma16(sacc[mi][ni], qa[mi], kb);
        }

        #pragma unroll
        for (int mi = 0; mi < 2; mi++)
            #pragma unroll
            for (int ni = 0; ni < 4; ni++) {
                sacc[mi][ni][0] = ex2(sacc[mi][ni][0]);
                sacc[mi][ni][1] = ex2(sacc[mi][ni][1]);
                sacc[mi][ni][2] = ex2(sacc[mi][ni][2]);
                sacc[mi][ni][3] = ex2(sacc[mi][ni][3]);
            }

        #pragma unroll
        for (int kk = 0; kk < 2; kk++) {
            uint32_t pa[2][4];
            #pragma unroll
            for (int mi = 0; mi < 2; mi++) {
                pa[mi][0] = packbf(sacc[mi][2*kk  ][0], sacc[mi][2*kk  ][1]);
                pa[mi][1] = packbf(sacc[mi][2*kk  ][2], sacc[mi][2*kk  ][3]);
                pa[mi][2] = packbf(sacc[mi][2*kk+1][0], sacc[mi][2*kk+1][1]);
                pa[mi][3] = packbf(sacc[mi][2*kk+1][2], sacc[mi][2*kk+1][3]);
            }
            #pragma unroll
            for (int nd = 0; nd < 3; nd++) {
                uint32_t vb[2];
                ldm_x2_t(vb, sV + 2*((s0 + kk*16 + (lane & 15))*24 + nd*8));
                #pragma unroll
                for (int mi = 0; mi < 2; mi++)
                    mma16(oacc[mi][nd], pa[mi], vb);
            }
        }
    }

    #pragma unroll
    for (int mi = 0; mi < 2; mi++) {
        #pragma unroll
        for (int rr = 0; rr < 2; rr++) {
            float l = __shfl_sync(0xffffffffu, oacc[mi][2][rr*2], lane & ~3);
            float il = 1.0f / l;
            int row = m0 + mi*16 + rr*8 + g;
            long oidx = ((long)h*NTOK + seq*TT + row) * HD;
            #pragma unroll
            for (int nd = 0; nd < 2; nd++) {
                *(uint32_t*)&out[oidx + nd*8 + 2*tig] =
                    packbf(oacc[mi][nd][rr*2+0]*il, oacc[mi][nd][rr*2+1]*il);
            }
        }
    }
}

// -------------------------------- launch ----------------------------------------
extern "C" void kernel_launch(void* const* d_in, const int* in_sizes, int n_in,
                              void* d_out, int out_size)
{
    const float* x     = (const float*)d_in[0];
    const float* ln1g  = (const float*)d_in[1];
    const float* ln1b  = (const float*)d_in[2];
    const float* qkvw  = (const float*)d_in[3];
    const float* qkvb  = (const float*)d_in[4];
    const float* projw = (const float*)d_in[5];
    const float* projb = (const float*)d_in[6];
    const float* ls    = (const float*)d_in[7];
    const float* rpb   = (const float*)d_in[8];
    const float* ln2g  = (const float*)d_in[9];
    const float* ln2b  = (const float*)d_in[10];
    const float* w1    = (const float*)d_in[11];
    const float* b1    = (const float*)d_in[12];
    const float* w2    = (const float*)d_in[13];
    const float* b2    = (const float*)d_in[14];
    float* out = (float*)d_out;

    bf16 *qkv, *attn, *z, *hb, *wbuf;
    float *xf;
    cudaGetSymbolAddress((void**)&qkv,  g_qkv);
    cudaGetSymbolAddress((void**)&attn, g_attn);
    cudaGetSymbolAddress((void**)&xf,   g_xf);
    cudaGetSymbolAddress((void**)&z,    g_z);
    cudaGetSymbolAddress((void**)&hb,   g_h);
    cudaGetSymbolAddress((void**)&wbuf, g_w);

    cudaFuncSetAttribute(qkvln_kernel, cudaFuncAttributeMaxDynamicSharedMemorySize, QKV_SMEM);
    cudaFuncSetAttribute(mma_gemm<128, 128, 1, 1>, cudaFuncAttributeMaxDynamicSharedMemorySize, GEMM_SMEM);
    cudaFuncSetAttribute(mma_gemm<128, 512, 2, 0>, cudaFuncAttributeMaxDynamicSharedMemorySize, GEMM_SMEM);
    cudaFuncSetAttribute(mma_gemm<512, 128, 3, 0>, cudaFuncAttributeMaxDynamicSharedMemorySize, GEMM_SMEM);

    // 0) weights -> bf16
    wprep_kernel<<<(WTOTAL + 255)/256, 256>>>(qkvw, projw, w1, w2, wbuf);
    // 1) fused gather+LN1+QKV -> head-major bf16 q/k/v
    qkvln_kernel<<<NTOK/BM, 256, QKV_SMEM>>>(x, ln1g, ln1b, wbuf + WOFF_QKV, qkvb, qkv);
    // 2) bf16 tensor-core attention
    attn_bf16_kernel<<<dim3(SEQS, HH), 256>>>(qkv, ls, rpb, attn);
    // 3) proj + residual -> xf (fp32), fused LN2 -> z (bf16)
    mma_gemm<128, 128, 1, 1><<<dim3(1, NTOK/BM), 256, GEMM_SMEM>>>(
        attn, wbuf + WOFF_PROJ, projb, x, xf, z, ln2g, ln2b);
    // 4) FFN1 + exact GELU -> h (bf16)
    mma_gemm<128, 512, 2, 0><<<dim3(4, NTOK/BM), 256, GEMM_SMEM>>>(
        z, wbuf + WOFF_W1, b1, nullptr, nullptr, hb, nullptr, nullptr);
    // 5) FFN2 + residual -> scatter fp32 (B,T,V,D) output
    mma_gemm<512, 128, 3, 0><<<dim3(1, NTOK/BM), 256, GEMM_SMEM>>>(
        hb, wbuf + WOFF_W2, b2, xf, out, nullptr, nullptr, nullptr);
}